// round 10
// baseline (speedup 1.0000x reference)
#include <cuda_runtime.h>
#include <cuda_bf16.h>
#include <mma.h>
#include <math.h>
#include <stdint.h>

using namespace nvcuda;

#define NN 100000
#define EE 1600000
#define NB ((NN + 255) / 256)   // 391 scan blocks

// ---------------- device scratch (allocation-free: __device__ globals) ------
__device__ int   g_is64;
__device__ int   g_deg[NN];
__device__ int   g_off[NN + 1];
__device__ int   g_srcs[EE];
__device__ int   g_bsum[NB];
__device__ float g_agg[NN * 64];
__device__ float g_h1[NN * 128];
__device__ float g_hr[NN * 64];
__device__ float g_h2pre[NN * 64];
__device__ float g_pool[64];
__device__ float g_Z;
// bf16-split transposed weights: B[n][k], hi/lo
__device__ __nv_bfloat16 g_B1h[128 * 128];
__device__ __nv_bfloat16 g_B1l[128 * 128];
__device__ __nv_bfloat16 g_B2h[128 * 128];
__device__ __nv_bfloat16 g_B2l[128 * 128];

// ---------------- zero-init --------------------------------------------------
__global__ __launch_bounds__(256) void init_kernel() {
    int i = blockIdx.x * blockDim.x + threadIdx.x;
    if (i < NN) g_deg[i] = 0;
    if (i < 64) g_pool[i] = 0.f;
    if (i == 0) g_Z = 0.f;
}

// ---------------- edge_index dtype detection ---------------------------------
__global__ __launch_bounds__(32) void detect_kernel(const void* ei) {
    const long long* p = (const long long*)ei;
    int lane = threadIdx.x;
    long long v = p[lane * 7];
    bool ok = (v >= 0 && v < NN);
    unsigned m = __ballot_sync(0xffffffffu, ok);
    if (lane == 0) g_is64 = (m == 0xffffffffu) ? 1 : 0;
}

// ---------------- histogram of dst (reads edge_index directly) ---------------
__global__ __launch_bounds__(256) void hist_kernel(const void* ei) {
    int e = blockIdx.x * blockDim.x + threadIdx.x;
    if (e >= EE) return;
    int d;
    if (g_is64) d = (int)((const long long*)ei)[EE + e];
    else        d = ((const int*)ei)[EE + e];
    atomicAdd(&g_deg[d], 1);
}

// ---------------- CSR offsets: 3-phase parallel scan -------------------------
__global__ __launch_bounds__(256) void bsum_kernel() {
    __shared__ int sw[8];
    int i = blockIdx.x * 256 + threadIdx.x;
    int v = (i < NN) ? g_deg[i] : 0;
#pragma unroll
    for (int o = 16; o; o >>= 1) v += __shfl_down_sync(0xffffffffu, v, o);
    if ((threadIdx.x & 31) == 0) sw[threadIdx.x >> 5] = v;
    __syncthreads();
    if (threadIdx.x == 0) {
        int s = 0;
#pragma unroll
        for (int q = 0; q < 8; q++) s += sw[q];
        g_bsum[blockIdx.x] = s;
    }
}

__global__ __launch_bounds__(512) void bscan_kernel() {
    __shared__ int ss[512];
    const int t = threadIdx.x;
    int v = (t < NB) ? g_bsum[t] : 0;
    ss[t] = v;
    __syncthreads();
#pragma unroll 1
    for (int off = 1; off < 512; off <<= 1) {
        int tmp = (t >= off) ? ss[t - off] : 0;
        __syncthreads();
        ss[t] += tmp;
        __syncthreads();
    }
    if (t < NB) g_bsum[t] = (t > 0) ? ss[t - 1] : 0;
    if (t == 0) g_off[NN] = ss[NB - 1];
}

__global__ __launch_bounds__(256) void offsets_kernel() {
    __shared__ int sw[8];
    const int t = threadIdx.x;
    const int lane = t & 31, w = t >> 5;
    int i = blockIdx.x * 256 + t;
    int v = (i < NN) ? g_deg[i] : 0;
    int sc = v;
#pragma unroll
    for (int o = 1; o < 32; o <<= 1) {
        int n = __shfl_up_sync(0xffffffffu, sc, o);
        if (lane >= o) sc += n;
    }
    if (lane == 31) sw[w] = sc;
    __syncthreads();
    if (t < 8) {
        int a = sw[t];
#pragma unroll
        for (int o = 1; o < 8; o <<= 1) {
            int n = __shfl_up_sync(0x000000ffu, a, o);
            if (t >= o) a += n;
        }
        sw[t] = a;
    }
    __syncthreads();
    int base = g_bsum[blockIdx.x] + ((w > 0) ? sw[w - 1] : 0);
    if (i < NN) g_off[i] = base + sc - v;   // exclusive start
}

// scatter mutates g_off in place: afterwards g_off[d] = end(d);
// readers use beg = (d>0) ? g_off[d-1] : 0, end = g_off[d].
__global__ __launch_bounds__(256) void scatter_kernel(const void* ei) {
    int e = blockIdx.x * blockDim.x + threadIdx.x;
    if (e >= EE) return;
    int s, d;
    if (g_is64) {
        s = (int)((const long long*)ei)[e];
        d = (int)((const long long*)ei)[EE + e];
    } else {
        s = ((const int*)ei)[e];
        d = ((const int*)ei)[EE + e];
    }
    int pos = atomicAdd(&g_off[d], 1);
    g_srcs[pos] = s;
}

// ---------------- mean aggregation (warp per node, 4-way unrolled) ----------
__global__ __launch_bounds__(256) void agg_kernel(
    const float* __restrict__ feat, float* __restrict__ out)
{
    int w = (blockIdx.x * blockDim.x + threadIdx.x) >> 5;
    int lane = threadIdx.x & 31;
    if (w >= NN) return;
    int beg = (w > 0) ? g_off[w - 1] : 0;
    int end = g_off[w];
    int d = end - beg;
    const float2* __restrict__ F = reinterpret_cast<const float2*>(feat);
    float ax = 0.f, ay = 0.f;
    int j = beg;
    for (; j + 3 < end; j += 4) {
        int s0 = __ldg(&g_srcs[j]);
        int s1 = __ldg(&g_srcs[j + 1]);
        int s2 = __ldg(&g_srcs[j + 2]);
        int s3 = __ldg(&g_srcs[j + 3]);
        float2 v0 = F[s0 * 32 + lane];
        float2 v1 = F[s1 * 32 + lane];
        float2 v2 = F[s2 * 32 + lane];
        float2 v3 = F[s3 * 32 + lane];
        ax += (v0.x + v1.x) + (v2.x + v3.x);
        ay += (v0.y + v1.y) + (v2.y + v3.y);
    }
    for (; j < end; j++) {
        int s = __ldg(&g_srcs[j]);
        float2 v = F[s * 32 + lane];
        ax += v.x; ay += v.y;
    }
    float inv = 1.0f / fmaxf((float)d, 1.0f);
    float2 o; o.x = ax * inv; o.y = ay * inv;
    reinterpret_cast<float2*>(out)[w * 32 + lane] = o;
}

// ---------------- weight prep: transpose + bf16 hi/lo split ------------------
__global__ __launch_bounds__(256) void prep_weights_kernel(
    const float* __restrict__ W1l, const float* __restrict__ W1r,
    const float* __restrict__ W2l, const float* __restrict__ W2r)
{
    int idx = blockIdx.x * blockDim.x + threadIdx.x;
    if (idx >= 128 * 128) return;
    int n = idx >> 7, k = idx & 127;
    float v1 = (k < 64) ? __ldg(&W1l[k * 128 + n]) : __ldg(&W1r[(k - 64) * 128 + n]);
    __nv_bfloat16 h1 = __float2bfloat16(v1);
    g_B1h[idx] = h1;
    g_B1l[idx] = __float2bfloat16(v1 - __bfloat162float(h1));
    float v2 = (n < 64) ? __ldg(&W2r[k * 64 + n]) : __ldg(&W2l[k * 64 + (n - 64)]);
    __nv_bfloat16 h2 = __float2bfloat16(v2);
    g_B2h[idx] = h2;
    g_B2l[idx] = __float2bfloat16(v2 - __bfloat162float(h2));
}

// ---------------- wmma bf16-split GEMM (ldm=136 padded smem) -----------------
#define LDM 136
#define ABUF (128 * LDM * 2)     // 34816 bytes per buffer
#define SMEM_WM (4 * ABUF)       // 139264
#define NTILES ((NN + 127) / 128)

template <int MODE>
__global__ __launch_bounds__(256) void gemm_wmma_kernel(
    const float* __restrict__ A0, const float* __restrict__ A1,
    const __nv_bfloat16* __restrict__ Bh, const __nv_bfloat16* __restrict__ Bl,
    const float* __restrict__ bias,
    float* __restrict__ out0, float* __restrict__ out1)
{
    extern __shared__ char smem[];
    __nv_bfloat16* sAh = (__nv_bfloat16*)(smem);
    __nv_bfloat16* sAl = (__nv_bfloat16*)(smem + ABUF);
    __nv_bfloat16* sBh = (__nv_bfloat16*)(smem + 2 * ABUF);
    __nv_bfloat16* sBl = (__nv_bfloat16*)(smem + 3 * ABUF);
    float* sC = (float*)smem;                    // [128][132] epilogue buffer

    const int tid = threadIdx.x;
    const int row0 = blockIdx.x * 128;

    // ---- load B (hi/lo) with padded rows ----
    {
        const uint32_t* bh = (const uint32_t*)Bh;
        const uint32_t* bl = (const uint32_t*)Bl;
        uint32_t* dh = (uint32_t*)sBh;
        uint32_t* dl = (uint32_t*)sBl;
#pragma unroll 8
        for (int i = tid; i < 8192; i += 256) {
            int n = i >> 6, c = i & 63;
            dh[n * (LDM / 2) + c] = __ldg(&bh[i]);
            dl[n * (LDM / 2) + c] = __ldg(&bl[i]);
        }
    }
    // ---- load A rows, split fp32 -> bf16 hi/lo ----
#pragma unroll 4
    for (int i = tid; i < 4096; i += 256) {
        int row = i >> 5;
        int c4 = (i & 31) * 4;
        int grow = row0 + row;
        float4 v = make_float4(0.f, 0.f, 0.f, 0.f);
        if (grow < NN) {
            if (MODE == 0)
                v = (c4 < 64) ? __ldg((const float4*)(A0 + (size_t)grow * 64 + c4))
                              : __ldg((const float4*)(A1 + (size_t)grow * 64 + c4 - 64));
            else
                v = __ldg((const float4*)(A0 + (size_t)grow * 128 + c4));
        }
        __nv_bfloat162 h01 = __floats2bfloat162_rn(v.x, v.y);
        __nv_bfloat162 h23 = __floats2bfloat162_rn(v.z, v.w);
        __nv_bfloat162 l01 = __floats2bfloat162_rn(
            v.x - __bfloat162float(h01.x), v.y - __bfloat162float(h01.y));
        __nv_bfloat162 l23 = __floats2bfloat162_rn(
            v.z - __bfloat162float(h23.x), v.w - __bfloat162float(h23.y));
        uint2 hp, lp;
        hp.x = *(uint32_t*)&h01; hp.y = *(uint32_t*)&h23;
        lp.x = *(uint32_t*)&l01; lp.y = *(uint32_t*)&l23;
        *(uint2*)(sAh + row * LDM + c4) = hp;
        *(uint2*)(sAl + row * LDM + c4) = lp;
    }
    __syncthreads();

    const int wid = tid >> 5;
    const int wm = wid >> 1;
    const int wn = wid & 1;

    wmma::fragment<wmma::accumulator, 16, 16, 16, float> c[2][4];
#pragma unroll
    for (int i = 0; i < 2; i++)
#pragma unroll
        for (int j = 0; j < 4; j++) wmma::fill_fragment(c[i][j], 0.f);

#pragma unroll 1
    for (int pass = 0; pass < 3; pass++) {
        const __nv_bfloat16* pa = (pass == 2) ? sAl : sAh;
        const __nv_bfloat16* pb = (pass == 1) ? sBl : sBh;
#pragma unroll
        for (int kk = 0; kk < 128; kk += 16) {
            wmma::fragment<wmma::matrix_a, 16, 16, 16, __nv_bfloat16, wmma::row_major> a[2];
            wmma::fragment<wmma::matrix_b, 16, 16, 16, __nv_bfloat16, wmma::col_major> b[4];
#pragma unroll
            for (int i = 0; i < 2; i++)
                wmma::load_matrix_sync(a[i], pa + (wm * 32 + i * 16) * LDM + kk, LDM);
#pragma unroll
            for (int j = 0; j < 4; j++)
                wmma::load_matrix_sync(b[j], pb + (wn * 64 + j * 16) * LDM + kk, LDM);
#pragma unroll
            for (int i = 0; i < 2; i++)
#pragma unroll
                for (int j = 0; j < 4; j++)
                    wmma::mma_sync(c[i][j], a[i], b[j], c[i][j]);
        }
    }
    __syncthreads();

#pragma unroll
    for (int i = 0; i < 2; i++)
#pragma unroll
        for (int j = 0; j < 4; j++)
            wmma::store_matrix_sync(&sC[(wm * 32 + i * 16) * 132 + wn * 64 + j * 16],
                                    c[i][j], 132, wmma::mem_row_major);
    __syncthreads();

#pragma unroll 4
    for (int i = tid; i < 4096; i += 256) {
        int row = i >> 5;
        int c4 = (i & 31) * 4;
        int grow = row0 + row;
        if (grow >= NN) continue;
        float4 o;
        o.x = sC[row * 132 + c4];
        o.y = sC[row * 132 + c4 + 1];
        o.z = sC[row * 132 + c4 + 2];
        o.w = sC[row * 132 + c4 + 3];
        if (MODE == 0) {
            o.x = fmaxf(o.x + __ldg(&bias[c4]), 0.f);
            o.y = fmaxf(o.y + __ldg(&bias[c4 + 1]), 0.f);
            o.z = fmaxf(o.z + __ldg(&bias[c4 + 2]), 0.f);
            o.w = fmaxf(o.w + __ldg(&bias[c4 + 3]), 0.f);
            *(float4*)(out0 + (size_t)grow * 128 + c4) = o;
        } else {
            if (c4 < 64) *(float4*)(out0 + (size_t)grow * 64 + c4) = o;
            else         *(float4*)(out1 + (size_t)grow * 64 + c4 - 64) = o;
        }
    }
}

// ------- fused: agg2 gather + h2 + attention + exp + weighted pooling -------
// warp per node; lane holds dims (2*lane, 2*lane+1); 4-way unrolled gather
__global__ __launch_bounds__(256) void post_fused_kernel(
    const float* __restrict__ h2pre, const float* __restrict__ hr,
    const float* __restrict__ x,
    const float* __restrict__ b2, const float* __restrict__ Wa,
    const float* __restrict__ ba, const float* __restrict__ ctx,
    float* __restrict__ gpool, float* __restrict__ gZ)
{
    __shared__ float sWa[64 * 32];
    __shared__ float sba[32], sctx[32];
    __shared__ float sb2[64];
    __shared__ float spool[64];
    __shared__ float sZ;
    const int tid = threadIdx.x;
    for (int f = tid; f < 2048; f += 256) sWa[f] = __ldg(&Wa[f]);
    if (tid < 32) { sba[tid] = __ldg(&ba[tid]); sctx[tid] = __ldg(&ctx[tid]); }
    if (tid < 64) { sb2[tid] = __ldg(&b2[tid]); spool[tid] = 0.f; }
    if (tid == 64) sZ = 0.f;
    __syncthreads();

    const int w = tid >> 5, lane = tid & 31;
    const int i = blockIdx.x * 8 + w;
    if (i < NN) {
        int beg = (i > 0) ? g_off[i - 1] : 0;
        int end = g_off[i];
        int d = end - beg;
        const float2* __restrict__ F = reinterpret_cast<const float2*>(h2pre);
        float ax = 0.f, ay = 0.f;
        int j = beg;
        for (; j + 3 < end; j += 4) {
            int s0 = __ldg(&g_srcs[j]);
            int s1 = __ldg(&g_srcs[j + 1]);
            int s2 = __ldg(&g_srcs[j + 2]);
            int s3 = __ldg(&g_srcs[j + 3]);
            float2 v0 = F[s0 * 32 + lane];
            float2 v1 = F[s1 * 32 + lane];
            float2 v2 = F[s2 * 32 + lane];
            float2 v3 = F[s3 * 32 + lane];
            ax += (v0.x + v1.x) + (v2.x + v3.x);
            ay += (v0.y + v1.y) + (v2.y + v3.y);
        }
        for (; j < end; j++) {
            int s = __ldg(&g_srcs[j]);
            float2 v = F[s * 32 + lane];
            ax += v.x; ay += v.y;
        }
        float inv = 1.0f / fmaxf((float)d, 1.0f);
        float2 hrv = reinterpret_cast<const float2*>(hr)[i * 32 + lane];
        float v0 = fmaxf(ax * inv + hrv.x + sb2[2 * lane], 0.f);
        float v1 = fmaxf(ay * inv + hrv.y + sb2[2 * lane + 1], 0.f);

        float acc = 0.f;
#pragma unroll
        for (int k = 0; k < 32; k++) {
            float hk0 = __shfl_sync(0xffffffffu, v0, k);
            float hk1 = __shfl_sync(0xffffffffu, v1, k);
            acc += hk0 * sWa[(2 * k) * 32 + lane] + hk1 * sWa[(2 * k + 1) * 32 + lane];
        }
        float t = tanhf(acc + sba[lane]) * sctx[lane];
#pragma unroll
        for (int o = 16; o; o >>= 1) t += __shfl_xor_sync(0xffffffffu, t, o);
        t += 0.4f * __ldg(&x[i * 64 + 63]);
        float e = expf(t);     // logits bounded: no max pass needed
        atomicAdd(&spool[2 * lane], e * v0);
        atomicAdd(&spool[2 * lane + 1], e * v1);
        if (lane == 0) atomicAdd(&sZ, e);
    }
    __syncthreads();
    if (tid < 64) atomicAdd(&gpool[tid], spool[tid]);
    if (tid == 64) atomicAdd(gZ, sZ);
}

// ---------------- tiny head --------------------------------------------------
__global__ __launch_bounds__(32) void final_kernel(
    const float* __restrict__ gpool, const float* __restrict__ gZ,
    const float* __restrict__ Wc1, const float* __restrict__ bc1,
    const float* __restrict__ Wc2, const float* __restrict__ bc2,
    float* __restrict__ out)
{
    const int j = threadIdx.x;
    const float inv = 1.0f / ((float)NN * (*gZ));
    float acc = bc1[j];
    for (int k = 0; k < 64; k++)
        acc += gpool[k] * inv * Wc1[k * 32 + j];
    float zv = fmaxf(acc, 0.f);
    float s = zv * Wc2[j];
#pragma unroll
    for (int o = 16; o; o >>= 1) s += __shfl_xor_sync(0xffffffffu, s, o);
    if (j == 0) out[0] = 1.0f / (1.0f + expf(-(s + bc2[0])));
}

// ---------------- launch ------------------------------------------------------
extern "C" void kernel_launch(void* const* d_in, const int* in_sizes, int n_in,
                              void* d_out, int out_size) {
    const float* x   = (const float*)d_in[0];
    const void*  ei  = d_in[1];
    const float* W1l = (const float*)d_in[2];
    const float* W1r = (const float*)d_in[3];
    const float* b1  = (const float*)d_in[4];
    const float* W2l = (const float*)d_in[5];
    const float* W2r = (const float*)d_in[6];
    const float* b2  = (const float*)d_in[7];
    const float* Wa  = (const float*)d_in[8];
    const float* ba  = (const float*)d_in[9];
    const float* ctx = (const float*)d_in[10];
    const float* Wc1 = (const float*)d_in[11];
    const float* bc1 = (const float*)d_in[12];
    const float* Wc2 = (const float*)d_in[13];
    const float* bc2 = (const float*)d_in[14];
    float* out = (float*)d_out;

    void *ppool, *pz, *pagg, *ph1, *phr, *ph2pre;
    void *pB1h, *pB1l, *pB2h, *pB2l;
    cudaGetSymbolAddress(&ppool, g_pool);
    cudaGetSymbolAddress(&pz, g_Z);
    cudaGetSymbolAddress(&pagg, g_agg);
    cudaGetSymbolAddress(&ph1, g_h1);
    cudaGetSymbolAddress(&phr, g_hr);
    cudaGetSymbolAddress(&ph2pre, g_h2pre);
    cudaGetSymbolAddress(&pB1h, g_B1h);
    cudaGetSymbolAddress(&pB1l, g_B1l);
    cudaGetSymbolAddress(&pB2h, g_B2h);
    cudaGetSymbolAddress(&pB2l, g_B2l);

    cudaFuncSetAttribute(gemm_wmma_kernel<0>, cudaFuncAttributeMaxDynamicSharedMemorySize, SMEM_WM);
    cudaFuncSetAttribute(gemm_wmma_kernel<1>, cudaFuncAttributeMaxDynamicSharedMemorySize, SMEM_WM);

    init_kernel<<<(NN + 255) / 256, 256>>>();
    detect_kernel<<<1, 32>>>(ei);
    hist_kernel<<<(EE + 255) / 256, 256>>>(ei);

    // parallel CSR offsets (3-phase scan)
    bsum_kernel<<<NB, 256>>>();
    bscan_kernel<<<1, 512>>>();
    offsets_kernel<<<NB, 256>>>();

    scatter_kernel<<<(EE + 255) / 256, 256>>>(ei);   // mutates g_off -> ends

    prep_weights_kernel<<<64, 256>>>(W1l, W1r, W2l, W2r);

    // agg1 = mean_agg(x)
    agg_kernel<<<(NN * 32 + 255) / 256, 256>>>(x, (float*)pagg);

    // h1 = relu([agg1|x] @ [W1_l;W1_r] + b1)
    gemm_wmma_kernel<0><<<NTILES, 256, SMEM_WM>>>(
        (const float*)pagg, x,
        (const __nv_bfloat16*)pB1h, (const __nv_bfloat16*)pB1l,
        b1, (float*)ph1, nullptr);

    // [hr | h2pre] = h1 @ [W2_r | W2_l]
    gemm_wmma_kernel<1><<<NTILES, 256, SMEM_WM>>>(
        (const float*)ph1, nullptr,
        (const __nv_bfloat16*)pB2h, (const __nv_bfloat16*)pB2l,
        nullptr, (float*)phr, (float*)ph2pre);

    // fused: gather(mean h2pre) + h2 + attention + exp + weighted pool
    post_fused_kernel<<<(NN + 7) / 8, 256>>>(
        (const float*)ph2pre, (const float*)phr, x, b2, Wa, ba, ctx,
        (float*)ppool, (float*)pz);

    final_kernel<<<1, 32>>>((const float*)ppool, (const float*)pz,
                            Wc1, bc1, Wc2, bc2, out);
}

// round 11
// speedup vs baseline: 1.4483x; 1.4483x over previous
#include <cuda_runtime.h>
#include <cuda_bf16.h>
#include <mma.h>
#include <math.h>
#include <stdint.h>

using namespace nvcuda;

#define NN 100000
#define EE 1600000
#define NB ((NN + 255) / 256)   // 391 scan blocks

// ---------------- device scratch (allocation-free: __device__ globals) ------
__device__ int   g_is64;
__device__ int   g_deg[NN];
__device__ int   g_off[NN + 1];
__device__ int   g_srcs[EE];
__device__ int   g_bsum[NB];
__device__ float g_agg[NN * 64];
__device__ float g_h1[NN * 128];
__device__ float g_hr[NN * 64];
__device__ float g_h2pre[NN * 64];
__device__ float g_pool[64];
__device__ float g_Z;
// bf16-split transposed weights: B[n][k], hi/lo
__device__ __nv_bfloat16 g_B1h[128 * 128];
__device__ __nv_bfloat16 g_B1l[128 * 128];
__device__ __nv_bfloat16 g_B2h[128 * 128];
__device__ __nv_bfloat16 g_B2l[128 * 128];

// ---------------- zero-init --------------------------------------------------
__global__ __launch_bounds__(256) void init_kernel() {
    int i = blockIdx.x * blockDim.x + threadIdx.x;
    if (i < NN) g_deg[i] = 0;
    if (i < 64) g_pool[i] = 0.f;
    if (i == 0) g_Z = 0.f;
}

// ---------------- edge_index dtype detection ---------------------------------
__global__ __launch_bounds__(32) void detect_kernel(const void* ei) {
    const long long* p = (const long long*)ei;
    int lane = threadIdx.x;
    long long v = p[lane * 7];
    bool ok = (v >= 0 && v < NN);
    unsigned m = __ballot_sync(0xffffffffu, ok);
    if (lane == 0) g_is64 = (m == 0xffffffffu) ? 1 : 0;
}

// ---------------- histogram of dst (reads edge_index directly) ---------------
__global__ __launch_bounds__(256) void hist_kernel(const void* ei) {
    int e = blockIdx.x * blockDim.x + threadIdx.x;
    if (e >= EE) return;
    int d;
    if (g_is64) d = (int)((const long long*)ei)[EE + e];
    else        d = ((const int*)ei)[EE + e];
    atomicAdd(&g_deg[d], 1);
}

// ---------------- CSR offsets: 3-phase parallel scan -------------------------
__global__ __launch_bounds__(256) void bsum_kernel() {
    __shared__ int sw[8];
    int i = blockIdx.x * 256 + threadIdx.x;
    int v = (i < NN) ? g_deg[i] : 0;
#pragma unroll
    for (int o = 16; o; o >>= 1) v += __shfl_down_sync(0xffffffffu, v, o);
    if ((threadIdx.x & 31) == 0) sw[threadIdx.x >> 5] = v;
    __syncthreads();
    if (threadIdx.x == 0) {
        int s = 0;
#pragma unroll
        for (int q = 0; q < 8; q++) s += sw[q];
        g_bsum[blockIdx.x] = s;
    }
}

__global__ __launch_bounds__(512) void bscan_kernel() {
    __shared__ int ss[512];
    const int t = threadIdx.x;
    int v = (t < NB) ? g_bsum[t] : 0;
    ss[t] = v;
    __syncthreads();
#pragma unroll 1
    for (int off = 1; off < 512; off <<= 1) {
        int tmp = (t >= off) ? ss[t - off] : 0;
        __syncthreads();
        ss[t] += tmp;
        __syncthreads();
    }
    if (t < NB) g_bsum[t] = (t > 0) ? ss[t - 1] : 0;
    if (t == 0) g_off[NN] = ss[NB - 1];
}

__global__ __launch_bounds__(256) void offsets_kernel() {
    __shared__ int sw[8];
    const int t = threadIdx.x;
    const int lane = t & 31, w = t >> 5;
    int i = blockIdx.x * 256 + t;
    int v = (i < NN) ? g_deg[i] : 0;
    int sc = v;
#pragma unroll
    for (int o = 1; o < 32; o <<= 1) {
        int n = __shfl_up_sync(0xffffffffu, sc, o);
        if (lane >= o) sc += n;
    }
    if (lane == 31) sw[w] = sc;
    __syncthreads();
    if (t < 8) {
        int a = sw[t];
#pragma unroll
        for (int o = 1; o < 8; o <<= 1) {
            int n = __shfl_up_sync(0x000000ffu, a, o);
            if (t >= o) a += n;
        }
        sw[t] = a;
    }
    __syncthreads();
    int base = g_bsum[blockIdx.x] + ((w > 0) ? sw[w - 1] : 0);
    if (i < NN) g_off[i] = base + sc - v;   // exclusive start
}

// scatter mutates g_off in place: afterwards g_off[d] = end(d);
// readers use beg = (d>0) ? g_off[d-1] : 0, end = g_off[d].
__global__ __launch_bounds__(256) void scatter_kernel(const void* ei) {
    int e = blockIdx.x * blockDim.x + threadIdx.x;
    if (e >= EE) return;
    int s, d;
    if (g_is64) {
        s = (int)((const long long*)ei)[e];
        d = (int)((const long long*)ei)[EE + e];
    } else {
        s = ((const int*)ei)[e];
        d = ((const int*)ei)[EE + e];
    }
    int pos = atomicAdd(&g_off[d], 1);
    g_srcs[pos] = s;
}

// ---------------- mean aggregation (warp per node, post-scatter offsets) ----
__global__ __launch_bounds__(256) void agg_kernel(
    const float* __restrict__ feat, float* __restrict__ out)
{
    int w = (blockIdx.x * blockDim.x + threadIdx.x) >> 5;
    int lane = threadIdx.x & 31;
    if (w >= NN) return;
    int beg = (w > 0) ? g_off[w - 1] : 0;
    int end = g_off[w];
    int d = end - beg;
    const float2* __restrict__ F = reinterpret_cast<const float2*>(feat);
    float ax = 0.f, ay = 0.f;
    int j = beg;
    for (; j + 1 < end; j += 2) {
        int s0 = __ldg(&g_srcs[j]);
        int s1 = __ldg(&g_srcs[j + 1]);
        float2 v0 = F[s0 * 32 + lane];
        float2 v1 = F[s1 * 32 + lane];
        ax += v0.x + v1.x;
        ay += v0.y + v1.y;
    }
    if (j < end) {
        int s = __ldg(&g_srcs[j]);
        float2 v = F[s * 32 + lane];
        ax += v.x; ay += v.y;
    }
    float inv = 1.0f / fmaxf((float)d, 1.0f);
    float2 o; o.x = ax * inv; o.y = ay * inv;
    reinterpret_cast<float2*>(out)[w * 32 + lane] = o;
}

// ---------------- weight prep: transpose + bf16 hi/lo split ------------------
__global__ __launch_bounds__(256) void prep_weights_kernel(
    const float* __restrict__ W1l, const float* __restrict__ W1r,
    const float* __restrict__ W2l, const float* __restrict__ W2r)
{
    int idx = blockIdx.x * blockDim.x + threadIdx.x;
    if (idx >= 128 * 128) return;
    int n = idx >> 7, k = idx & 127;
    float v1 = (k < 64) ? __ldg(&W1l[k * 128 + n]) : __ldg(&W1r[(k - 64) * 128 + n]);
    __nv_bfloat16 h1 = __float2bfloat16(v1);
    g_B1h[idx] = h1;
    g_B1l[idx] = __float2bfloat16(v1 - __bfloat162float(h1));
    float v2 = (n < 64) ? __ldg(&W2r[k * 64 + n]) : __ldg(&W2l[k * 64 + (n - 64)]);
    __nv_bfloat16 h2 = __float2bfloat16(v2);
    g_B2h[idx] = h2;
    g_B2l[idx] = __float2bfloat16(v2 - __bfloat162float(h2));
}

// ---------------- wmma bf16-split GEMM (ldm=136 padded smem) -----------------
#define LDM 136
#define ABUF (128 * LDM * 2)     // 34816 bytes per buffer
#define SMEM_WM (4 * ABUF)       // 139264
#define NTILES ((NN + 127) / 128)

// MODE 0: A=[agg|x], out0 = relu(acc + bias) -> h1 fp32 (stride 128)
// MODE 1: A=h1, out0 = acc[:, :64] -> hr, out1 = acc[:, 64:] -> h2pre
template <int MODE>
__global__ __launch_bounds__(256) void gemm_wmma_kernel(
    const float* __restrict__ A0, const float* __restrict__ A1,
    const __nv_bfloat16* __restrict__ Bh, const __nv_bfloat16* __restrict__ Bl,
    const float* __restrict__ bias,
    float* __restrict__ out0, float* __restrict__ out1)
{
    extern __shared__ char smem[];
    __nv_bfloat16* sAh = (__nv_bfloat16*)(smem);
    __nv_bfloat16* sAl = (__nv_bfloat16*)(smem + ABUF);
    __nv_bfloat16* sBh = (__nv_bfloat16*)(smem + 2 * ABUF);
    __nv_bfloat16* sBl = (__nv_bfloat16*)(smem + 3 * ABUF);
    float* sC = (float*)smem;                    // [128][132] epilogue buffer

    const int tid = threadIdx.x;
    const int row0 = blockIdx.x * 128;

    // ---- load B (hi/lo) with padded rows ----
    {
        const uint32_t* bh = (const uint32_t*)Bh;
        const uint32_t* bl = (const uint32_t*)Bl;
        uint32_t* dh = (uint32_t*)sBh;
        uint32_t* dl = (uint32_t*)sBl;
#pragma unroll 8
        for (int i = tid; i < 8192; i += 256) {
            int n = i >> 6, c = i & 63;
            dh[n * (LDM / 2) + c] = __ldg(&bh[i]);
            dl[n * (LDM / 2) + c] = __ldg(&bl[i]);
        }
    }
    // ---- load A rows, split fp32 -> bf16 hi/lo ----
#pragma unroll 4
    for (int i = tid; i < 4096; i += 256) {
        int row = i >> 5;
        int c4 = (i & 31) * 4;
        int grow = row0 + row;
        float4 v = make_float4(0.f, 0.f, 0.f, 0.f);
        if (grow < NN) {
            if (MODE == 0)
                v = (c4 < 64) ? __ldg((const float4*)(A0 + (size_t)grow * 64 + c4))
                              : __ldg((const float4*)(A1 + (size_t)grow * 64 + c4 - 64));
            else
                v = __ldg((const float4*)(A0 + (size_t)grow * 128 + c4));
        }
        __nv_bfloat162 h01 = __floats2bfloat162_rn(v.x, v.y);
        __nv_bfloat162 h23 = __floats2bfloat162_rn(v.z, v.w);
        __nv_bfloat162 l01 = __floats2bfloat162_rn(
            v.x - __bfloat162float(h01.x), v.y - __bfloat162float(h01.y));
        __nv_bfloat162 l23 = __floats2bfloat162_rn(
            v.z - __bfloat162float(h23.x), v.w - __bfloat162float(h23.y));
        uint2 hp, lp;
        hp.x = *(uint32_t*)&h01; hp.y = *(uint32_t*)&h23;
        lp.x = *(uint32_t*)&l01; lp.y = *(uint32_t*)&l23;
        *(uint2*)(sAh + row * LDM + c4) = hp;
        *(uint2*)(sAl + row * LDM + c4) = lp;
    }
    __syncthreads();

    const int wid = tid >> 5;
    const int wm = wid >> 1;
    const int wn = wid & 1;

    wmma::fragment<wmma::accumulator, 16, 16, 16, float> c[2][4];
#pragma unroll
    for (int i = 0; i < 2; i++)
#pragma unroll
        for (int j = 0; j < 4; j++) wmma::fill_fragment(c[i][j], 0.f);

#pragma unroll 1
    for (int pass = 0; pass < 3; pass++) {
        const __nv_bfloat16* pa = (pass == 2) ? sAl : sAh;
        const __nv_bfloat16* pb = (pass == 1) ? sBl : sBh;
#pragma unroll
        for (int kk = 0; kk < 128; kk += 16) {
            wmma::fragment<wmma::matrix_a, 16, 16, 16, __nv_bfloat16, wmma::row_major> a[2];
            wmma::fragment<wmma::matrix_b, 16, 16, 16, __nv_bfloat16, wmma::col_major> b[4];
#pragma unroll
            for (int i = 0; i < 2; i++)
                wmma::load_matrix_sync(a[i], pa + (wm * 32 + i * 16) * LDM + kk, LDM);
#pragma unroll
            for (int j = 0; j < 4; j++)
                wmma::load_matrix_sync(b[j], pb + (wn * 64 + j * 16) * LDM + kk, LDM);
#pragma unroll
            for (int i = 0; i < 2; i++)
#pragma unroll
                for (int j = 0; j < 4; j++)
                    wmma::mma_sync(c[i][j], a[i], b[j], c[i][j]);
        }
    }
    __syncthreads();

#pragma unroll
    for (int i = 0; i < 2; i++)
#pragma unroll
        for (int j = 0; j < 4; j++)
            wmma::store_matrix_sync(&sC[(wm * 32 + i * 16) * 132 + wn * 64 + j * 16],
                                    c[i][j], 132, wmma::mem_row_major);
    __syncthreads();

#pragma unroll 4
    for (int i = tid; i < 4096; i += 256) {
        int row = i >> 5;
        int c4 = (i & 31) * 4;
        int grow = row0 + row;
        if (grow >= NN) continue;
        float4 o;
        o.x = sC[row * 132 + c4];
        o.y = sC[row * 132 + c4 + 1];
        o.z = sC[row * 132 + c4 + 2];
        o.w = sC[row * 132 + c4 + 3];
        if (MODE == 0) {
            o.x = fmaxf(o.x + __ldg(&bias[c4]), 0.f);
            o.y = fmaxf(o.y + __ldg(&bias[c4 + 1]), 0.f);
            o.z = fmaxf(o.z + __ldg(&bias[c4 + 2]), 0.f);
            o.w = fmaxf(o.w + __ldg(&bias[c4 + 3]), 0.f);
            *(float4*)(out0 + (size_t)grow * 128 + c4) = o;
        } else {
            if (c4 < 64) *(float4*)(out0 + (size_t)grow * 64 + c4) = o;
            else         *(float4*)(out1 + (size_t)grow * 64 + c4 - 64) = o;
        }
    }
}

// ------- fused: agg2 gather + h2 + attention + exp + weighted pooling -------
// warp per node; lane holds dims (2*lane, 2*lane+1)
__global__ __launch_bounds__(256) void post_fused_kernel(
    const float* __restrict__ h2pre, const float* __restrict__ hr,
    const float* __restrict__ x,
    const float* __restrict__ b2, const float* __restrict__ Wa,
    const float* __restrict__ ba, const float* __restrict__ ctx,
    float* __restrict__ gpool, float* __restrict__ gZ)
{
    __shared__ float sWa[64 * 32];
    __shared__ float sba[32], sctx[32];
    __shared__ float sb2[64];
    __shared__ float spool[64];
    __shared__ float sZ;
    const int tid = threadIdx.x;
    for (int f = tid; f < 2048; f += 256) sWa[f] = __ldg(&Wa[f]);
    if (tid < 32) { sba[tid] = __ldg(&ba[tid]); sctx[tid] = __ldg(&ctx[tid]); }
    if (tid < 64) { sb2[tid] = __ldg(&b2[tid]); spool[tid] = 0.f; }
    if (tid == 64) sZ = 0.f;
    __syncthreads();

    const int w = tid >> 5, lane = tid & 31;
    const int i = blockIdx.x * 8 + w;
    if (i < NN) {
        int beg = (i > 0) ? g_off[i - 1] : 0;
        int end = g_off[i];
        int d = end - beg;
        const float2* __restrict__ F = reinterpret_cast<const float2*>(h2pre);
        float ax = 0.f, ay = 0.f;
        int j = beg;
        for (; j + 1 < end; j += 2) {
            int s0 = __ldg(&g_srcs[j]);
            int s1 = __ldg(&g_srcs[j + 1]);
            float2 v0 = F[s0 * 32 + lane];
            float2 v1 = F[s1 * 32 + lane];
            ax += v0.x + v1.x;
            ay += v0.y + v1.y;
        }
        if (j < end) {
            int s = __ldg(&g_srcs[j]);
            float2 v = F[s * 32 + lane];
            ax += v.x; ay += v.y;
        }
        float inv = 1.0f / fmaxf((float)d, 1.0f);
        float2 hrv = reinterpret_cast<const float2*>(hr)[i * 32 + lane];
        float v0 = fmaxf(ax * inv + hrv.x + sb2[2 * lane], 0.f);
        float v1 = fmaxf(ay * inv + hrv.y + sb2[2 * lane + 1], 0.f);

        float acc = 0.f;
#pragma unroll
        for (int k = 0; k < 32; k++) {
            float hk0 = __shfl_sync(0xffffffffu, v0, k);
            float hk1 = __shfl_sync(0xffffffffu, v1, k);
            acc += hk0 * sWa[(2 * k) * 32 + lane] + hk1 * sWa[(2 * k + 1) * 32 + lane];
        }
        float t = tanhf(acc + sba[lane]) * sctx[lane];
#pragma unroll
        for (int o = 16; o; o >>= 1) t += __shfl_xor_sync(0xffffffffu, t, o);
        t += 0.4f * __ldg(&x[i * 64 + 63]);
        float e = expf(t);     // logits bounded: no max pass needed
        atomicAdd(&spool[2 * lane], e * v0);
        atomicAdd(&spool[2 * lane + 1], e * v1);
        if (lane == 0) atomicAdd(&sZ, e);
    }
    __syncthreads();
    if (tid < 64) atomicAdd(&gpool[tid], spool[tid]);
    if (tid == 64) atomicAdd(gZ, sZ);
}

// ---------------- tiny head --------------------------------------------------
__global__ __launch_bounds__(32) void final_kernel(
    const float* __restrict__ gpool, const float* __restrict__ gZ,
    const float* __restrict__ Wc1, const float* __restrict__ bc1,
    const float* __restrict__ Wc2, const float* __restrict__ bc2,
    float* __restrict__ out)
{
    const int j = threadIdx.x;
    const float inv = 1.0f / ((float)NN * (*gZ));
    float acc = bc1[j];
    for (int k = 0; k < 64; k++)
        acc += gpool[k] * inv * Wc1[k * 32 + j];
    float zv = fmaxf(acc, 0.f);
    float s = zv * Wc2[j];
#pragma unroll
    for (int o = 16; o; o >>= 1) s += __shfl_xor_sync(0xffffffffu, s, o);
    if (j == 0) out[0] = 1.0f / (1.0f + expf(-(s + bc2[0])));
}

// ---------------- launch ------------------------------------------------------
extern "C" void kernel_launch(void* const* d_in, const int* in_sizes, int n_in,
                              void* d_out, int out_size) {
    const float* x   = (const float*)d_in[0];
    const void*  ei  = d_in[1];
    const float* W1l = (const float*)d_in[2];
    const float* W1r = (const float*)d_in[3];
    const float* b1  = (const float*)d_in[4];
    const float* W2l = (const float*)d_in[5];
    const float* W2r = (const float*)d_in[6];
    const float* b2  = (const float*)d_in[7];
    const float* Wa  = (const float*)d_in[8];
    const float* ba  = (const float*)d_in[9];
    const float* ctx = (const float*)d_in[10];
    const float* Wc1 = (const float*)d_in[11];
    const float* bc1 = (const float*)d_in[12];
    const float* Wc2 = (const float*)d_in[13];
    const float* bc2 = (const float*)d_in[14];
    float* out = (float*)d_out;

    void *ppool, *pz, *pagg, *ph1, *phr, *ph2pre;
    void *pB1h, *pB1l, *pB2h, *pB2l;
    cudaGetSymbolAddress(&ppool, g_pool);
    cudaGetSymbolAddress(&pz, g_Z);
    cudaGetSymbolAddress(&pagg, g_agg);
    cudaGetSymbolAddress(&ph1, g_h1);
    cudaGetSymbolAddress(&phr, g_hr);
    cudaGetSymbolAddress(&ph2pre, g_h2pre);
    cudaGetSymbolAddress(&pB1h, g_B1h);
    cudaGetSymbolAddress(&pB1l, g_B1l);
    cudaGetSymbolAddress(&pB2h, g_B2h);
    cudaGetSymbolAddress(&pB2l, g_B2l);

    cudaFuncSetAttribute(gemm_wmma_kernel<0>, cudaFuncAttributeMaxDynamicSharedMemorySize, SMEM_WM);
    cudaFuncSetAttribute(gemm_wmma_kernel<1>, cudaFuncAttributeMaxDynamicSharedMemorySize, SMEM_WM);

    init_kernel<<<(NN + 255) / 256, 256>>>();
    detect_kernel<<<1, 32>>>(ei);
    hist_kernel<<<(EE + 255) / 256, 256>>>(ei);

    // parallel CSR offsets (3-phase scan)
    bsum_kernel<<<NB, 256>>>();
    bscan_kernel<<<1, 512>>>();
    offsets_kernel<<<NB, 256>>>();

    scatter_kernel<<<(EE + 255) / 256, 256>>>(ei);   // mutates g_off -> ends

    prep_weights_kernel<<<64, 256>>>(W1l, W1r, W2l, W2r);

    // agg1 = mean_agg(x)
    agg_kernel<<<(NN * 32 + 255) / 256, 256>>>(x, (float*)pagg);

    // h1 = relu([agg1|x] @ [W1_l;W1_r] + b1)
    gemm_wmma_kernel<0><<<NTILES, 256, SMEM_WM>>>(
        (const float*)pagg, x,
        (const __nv_bfloat16*)pB1h, (const __nv_bfloat16*)pB1l,
        b1, (float*)ph1, nullptr);

    // [hr | h2pre] = h1 @ [W2_r | W2_l]
    gemm_wmma_kernel<1><<<NTILES, 256, SMEM_WM>>>(
        (const float*)ph1, nullptr,
        (const __nv_bfloat16*)pB2h, (const __nv_bfloat16*)pB2l,
        nullptr, (float*)phr, (float*)ph2pre);

    // fused: gather(mean h2pre) + h2 + attention + exp + weighted pool
    post_fused_kernel<<<(NN + 7) / 8, 256>>>(
        (const float*)ph2pre, (const float*)phr, x, b2, Wa, ba, ctx,
        (float*)ppool, (float*)pz);

    final_kernel<<<1, 32>>>((const float*)ppool, (const float*)pz,
                            Wc1, bc1, Wc2, bc2, out);
}

// round 12
// speedup vs baseline: 1.5655x; 1.0809x over previous
#include <cuda_runtime.h>
#include <cuda_bf16.h>
#include <mma.h>
#include <math.h>
#include <stdint.h>

using namespace nvcuda;

#define NN 100000
#define EE 1600000
#define NB ((NN + 255) / 256)   // 391 scan blocks

// ---------------- device scratch (allocation-free: __device__ globals) ------
__device__ int   g_is64;
__device__ int   g_deg[NN];
__device__ int   g_off[NN + 1];
__device__ int   g_srcs[EE];
__device__ int   g_bsum[NB];
__device__ float g_agg[NN * 64];
__device__ float g_hr[NN * 64];
__device__ float g_h2pre[NN * 64];
__device__ float g_pool[64];
__device__ float g_Z;
// bf16-split transposed weights: B[n][k], hi/lo
__device__ __nv_bfloat16 g_B1h[128 * 128];
__device__ __nv_bfloat16 g_B1l[128 * 128];
__device__ __nv_bfloat16 g_B2h[128 * 128];
__device__ __nv_bfloat16 g_B2l[128 * 128];

// ---------------- zero-init --------------------------------------------------
__global__ __launch_bounds__(256) void init_kernel() {
    int i = blockIdx.x * blockDim.x + threadIdx.x;
    if (i < NN) g_deg[i] = 0;
    if (i < 64) g_pool[i] = 0.f;
    if (i == 0) g_Z = 0.f;
}

// ---------------- edge_index dtype detection ---------------------------------
__global__ __launch_bounds__(32) void detect_kernel(const void* ei) {
    const long long* p = (const long long*)ei;
    int lane = threadIdx.x;
    long long v = p[lane * 7];
    bool ok = (v >= 0 && v < NN);
    unsigned m = __ballot_sync(0xffffffffu, ok);
    if (lane == 0) g_is64 = (m == 0xffffffffu) ? 1 : 0;
}

// ---------------- histogram of dst (reads edge_index directly) ---------------
__global__ __launch_bounds__(256) void hist_kernel(const void* ei) {
    int e = blockIdx.x * blockDim.x + threadIdx.x;
    if (e >= EE) return;
    int d;
    if (g_is64) d = (int)((const long long*)ei)[EE + e];
    else        d = ((const int*)ei)[EE + e];
    atomicAdd(&g_deg[d], 1);
}

// ---------------- CSR offsets: 3-phase parallel scan -------------------------
__global__ __launch_bounds__(256) void bsum_kernel() {
    __shared__ int sw[8];
    int i = blockIdx.x * 256 + threadIdx.x;
    int v = (i < NN) ? g_deg[i] : 0;
#pragma unroll
    for (int o = 16; o; o >>= 1) v += __shfl_down_sync(0xffffffffu, v, o);
    if ((threadIdx.x & 31) == 0) sw[threadIdx.x >> 5] = v;
    __syncthreads();
    if (threadIdx.x == 0) {
        int s = 0;
#pragma unroll
        for (int q = 0; q < 8; q++) s += sw[q];
        g_bsum[blockIdx.x] = s;
    }
}

__global__ __launch_bounds__(512) void bscan_kernel() {
    __shared__ int ss[512];
    const int t = threadIdx.x;
    int v = (t < NB) ? g_bsum[t] : 0;
    ss[t] = v;
    __syncthreads();
#pragma unroll 1
    for (int off = 1; off < 512; off <<= 1) {
        int tmp = (t >= off) ? ss[t - off] : 0;
        __syncthreads();
        ss[t] += tmp;
        __syncthreads();
    }
    if (t < NB) g_bsum[t] = (t > 0) ? ss[t - 1] : 0;
    if (t == 0) g_off[NN] = ss[NB - 1];
}

__global__ __launch_bounds__(256) void offsets_kernel() {
    __shared__ int sw[8];
    const int t = threadIdx.x;
    const int lane = t & 31, w = t >> 5;
    int i = blockIdx.x * 256 + t;
    int v = (i < NN) ? g_deg[i] : 0;
    int sc = v;
#pragma unroll
    for (int o = 1; o < 32; o <<= 1) {
        int n = __shfl_up_sync(0xffffffffu, sc, o);
        if (lane >= o) sc += n;
    }
    if (lane == 31) sw[w] = sc;
    __syncthreads();
    if (t < 8) {
        int a = sw[t];
#pragma unroll
        for (int o = 1; o < 8; o <<= 1) {
            int n = __shfl_up_sync(0x000000ffu, a, o);
            if (t >= o) a += n;
        }
        sw[t] = a;
    }
    __syncthreads();
    int base = g_bsum[blockIdx.x] + ((w > 0) ? sw[w - 1] : 0);
    if (i < NN) g_off[i] = base + sc - v;   // exclusive start
}

// scatter mutates g_off in place: afterwards g_off[d] = end(d);
// readers use beg = (d>0) ? g_off[d-1] : 0, end = g_off[d].
__global__ __launch_bounds__(256) void scatter_kernel(const void* ei) {
    int e = blockIdx.x * blockDim.x + threadIdx.x;
    if (e >= EE) return;
    int s, d;
    if (g_is64) {
        s = (int)((const long long*)ei)[e];
        d = (int)((const long long*)ei)[EE + e];
    } else {
        s = ((const int*)ei)[e];
        d = ((const int*)ei)[EE + e];
    }
    int pos = atomicAdd(&g_off[d], 1);
    g_srcs[pos] = s;
}

// ---------------- mean aggregation (warp per node, post-scatter offsets) ----
__global__ __launch_bounds__(256) void agg_kernel(
    const float* __restrict__ feat, float* __restrict__ out)
{
    int w = (blockIdx.x * blockDim.x + threadIdx.x) >> 5;
    int lane = threadIdx.x & 31;
    if (w >= NN) return;
    int beg = (w > 0) ? g_off[w - 1] : 0;
    int end = g_off[w];
    int d = end - beg;
    const float2* __restrict__ F = reinterpret_cast<const float2*>(feat);
    float ax = 0.f, ay = 0.f;
    int j = beg;
    for (; j + 1 < end; j += 2) {
        int s0 = __ldg(&g_srcs[j]);
        int s1 = __ldg(&g_srcs[j + 1]);
        float2 v0 = F[s0 * 32 + lane];
        float2 v1 = F[s1 * 32 + lane];
        ax += v0.x + v1.x;
        ay += v0.y + v1.y;
    }
    if (j < end) {
        int s = __ldg(&g_srcs[j]);
        float2 v = F[s * 32 + lane];
        ax += v.x; ay += v.y;
    }
    float inv = 1.0f / fmaxf((float)d, 1.0f);
    float2 o; o.x = ax * inv; o.y = ay * inv;
    reinterpret_cast<float2*>(out)[w * 32 + lane] = o;
}

// ---------------- weight prep: transpose + bf16 hi/lo split ------------------
__global__ __launch_bounds__(256) void prep_weights_kernel(
    const float* __restrict__ W1l, const float* __restrict__ W1r,
    const float* __restrict__ W2l, const float* __restrict__ W2r)
{
    int idx = blockIdx.x * blockDim.x + threadIdx.x;
    if (idx >= 128 * 128) return;
    int n = idx >> 7, k = idx & 127;
    float v1 = (k < 64) ? __ldg(&W1l[k * 128 + n]) : __ldg(&W1r[(k - 64) * 128 + n]);
    __nv_bfloat16 h1 = __float2bfloat16(v1);
    g_B1h[idx] = h1;
    g_B1l[idx] = __float2bfloat16(v1 - __bfloat162float(h1));
    float v2 = (n < 64) ? __ldg(&W2r[k * 64 + n]) : __ldg(&W2l[k * 64 + (n - 64)]);
    __nv_bfloat16 h2 = __float2bfloat16(v2);
    g_B2h[idx] = h2;
    g_B2l[idx] = __float2bfloat16(v2 - __bfloat162float(h2));
}

// ------- fused two-stage wmma GEMM: h1 never leaves shared memory -----------
// Stage1: acc1 = [agg|x]@B1 ; h1 = relu(acc1+b1) -> bf16 hi/lo in smem
// Stage2: acc2 = h1@B2 ; hr = acc2[:, :64], h2pre = acc2[:, 64:]
// smem regions (ABUF each): R0,R1 = stage1 A hi/lo -> sC -> stage2 B2 hi/lo
//                           R2,R3 = B1 hi/lo -> stage2 A (h1) hi/lo
#define LDM 136
#define ABUF (128 * LDM * 2)     // 34816 bytes per buffer
#define SMEM_WM (4 * ABUF)       // 139264
#define NTILES ((NN + 127) / 128)

__global__ __launch_bounds__(256) void gemm_fused_kernel(
    const float* __restrict__ agg, const float* __restrict__ x,
    const __nv_bfloat16* __restrict__ B1h, const __nv_bfloat16* __restrict__ B1l,
    const __nv_bfloat16* __restrict__ B2h, const __nv_bfloat16* __restrict__ B2l,
    const float* __restrict__ bias,
    float* __restrict__ hr, float* __restrict__ h2pre)
{
    extern __shared__ char smem[];
    __nv_bfloat16* R0 = (__nv_bfloat16*)(smem);
    __nv_bfloat16* R1 = (__nv_bfloat16*)(smem + ABUF);
    __nv_bfloat16* R2 = (__nv_bfloat16*)(smem + 2 * (size_t)ABUF);
    __nv_bfloat16* R3 = (__nv_bfloat16*)(smem + 3 * (size_t)ABUF);
    float* sC = (float*)smem;                    // [128][132], overlaps R0/R1

    const int tid = threadIdx.x;
    const int row0 = blockIdx.x * 128;
    const int wid = tid >> 5;
    const int wm = wid >> 1;
    const int wn = wid & 1;

    // ---- stage 1 loads: B1 -> R2/R3, A=[agg|x] split -> R0/R1 ----
    {
        const uint32_t* bh = (const uint32_t*)B1h;
        const uint32_t* bl = (const uint32_t*)B1l;
        uint32_t* dh = (uint32_t*)R2;
        uint32_t* dl = (uint32_t*)R3;
#pragma unroll 8
        for (int i = tid; i < 8192; i += 256) {
            int n = i >> 6, c = i & 63;
            dh[n * (LDM / 2) + c] = __ldg(&bh[i]);
            dl[n * (LDM / 2) + c] = __ldg(&bl[i]);
        }
    }
#pragma unroll 4
    for (int i = tid; i < 4096; i += 256) {
        int row = i >> 5;
        int c4 = (i & 31) * 4;
        int grow = row0 + row;
        float4 v = make_float4(0.f, 0.f, 0.f, 0.f);
        if (grow < NN)
            v = (c4 < 64) ? __ldg((const float4*)(agg + (size_t)grow * 64 + c4))
                          : __ldg((const float4*)(x + (size_t)grow * 64 + c4 - 64));
        __nv_bfloat162 h01 = __floats2bfloat162_rn(v.x, v.y);
        __nv_bfloat162 h23 = __floats2bfloat162_rn(v.z, v.w);
        __nv_bfloat162 l01 = __floats2bfloat162_rn(
            v.x - __bfloat162float(h01.x), v.y - __bfloat162float(h01.y));
        __nv_bfloat162 l23 = __floats2bfloat162_rn(
            v.z - __bfloat162float(h23.x), v.w - __bfloat162float(h23.y));
        uint2 hp, lp;
        hp.x = *(uint32_t*)&h01; hp.y = *(uint32_t*)&h23;
        lp.x = *(uint32_t*)&l01; lp.y = *(uint32_t*)&l23;
        *(uint2*)(R0 + row * LDM + c4) = hp;
        *(uint2*)(R1 + row * LDM + c4) = lp;
    }
    __syncthreads();

    // ---- stage 1 MMA: (Ah,B1h)+(Ah,B1l)+(Al,B1h) ----
    wmma::fragment<wmma::accumulator, 16, 16, 16, float> c[2][4];
#pragma unroll
    for (int i = 0; i < 2; i++)
#pragma unroll
        for (int j = 0; j < 4; j++) wmma::fill_fragment(c[i][j], 0.f);

#pragma unroll 1
    for (int pass = 0; pass < 3; pass++) {
        const __nv_bfloat16* pa = (pass == 2) ? R1 : R0;
        const __nv_bfloat16* pb = (pass == 1) ? R3 : R2;
#pragma unroll
        for (int kk = 0; kk < 128; kk += 16) {
            wmma::fragment<wmma::matrix_a, 16, 16, 16, __nv_bfloat16, wmma::row_major> a[2];
            wmma::fragment<wmma::matrix_b, 16, 16, 16, __nv_bfloat16, wmma::col_major> b[4];
#pragma unroll
            for (int i = 0; i < 2; i++)
                wmma::load_matrix_sync(a[i], pa + (wm * 32 + i * 16) * LDM + kk, LDM);
#pragma unroll
            for (int j = 0; j < 4; j++)
                wmma::load_matrix_sync(b[j], pb + (wn * 64 + j * 16) * LDM + kk, LDM);
#pragma unroll
            for (int i = 0; i < 2; i++)
#pragma unroll
                for (int j = 0; j < 4; j++)
                    wmma::mma_sync(c[i][j], a[i], b[j], c[i][j]);
        }
    }
    __syncthreads();   // A/B1 dead; R0/R1 become sC

    // ---- stage 1 epilogue: frags -> sC ----
#pragma unroll
    for (int i = 0; i < 2; i++)
#pragma unroll
        for (int j = 0; j < 4; j++)
            wmma::store_matrix_sync(&sC[(wm * 32 + i * 16) * 132 + wn * 64 + j * 16],
                                    c[i][j], 132, wmma::mem_row_major);
    __syncthreads();

    // ---- h1 = relu(sC + bias), split bf16 hi/lo -> R2/R3 (B1 dead) ----
#pragma unroll 4
    for (int i = tid; i < 4096; i += 256) {
        int row = i >> 5;
        int c4 = (i & 31) * 4;
        float4 v;
        v.x = fmaxf(sC[row * 132 + c4]     + __ldg(&bias[c4]),     0.f);
        v.y = fmaxf(sC[row * 132 + c4 + 1] + __ldg(&bias[c4 + 1]), 0.f);
        v.z = fmaxf(sC[row * 132 + c4 + 2] + __ldg(&bias[c4 + 2]), 0.f);
        v.w = fmaxf(sC[row * 132 + c4 + 3] + __ldg(&bias[c4 + 3]), 0.f);
        __nv_bfloat162 h01 = __floats2bfloat162_rn(v.x, v.y);
        __nv_bfloat162 h23 = __floats2bfloat162_rn(v.z, v.w);
        __nv_bfloat162 l01 = __floats2bfloat162_rn(
            v.x - __bfloat162float(h01.x), v.y - __bfloat162float(h01.y));
        __nv_bfloat162 l23 = __floats2bfloat162_rn(
            v.z - __bfloat162float(h23.x), v.w - __bfloat162float(h23.y));
        uint2 hp, lp;
        hp.x = *(uint32_t*)&h01; hp.y = *(uint32_t*)&h23;
        lp.x = *(uint32_t*)&l01; lp.y = *(uint32_t*)&l23;
        *(uint2*)(R2 + row * LDM + c4) = hp;
        *(uint2*)(R3 + row * LDM + c4) = lp;
    }
    __syncthreads();   // sC consumed; R0/R1 free for B2

    // ---- stage 2 loads: B2 -> R0/R1 ----
    {
        const uint32_t* bh = (const uint32_t*)B2h;
        const uint32_t* bl = (const uint32_t*)B2l;
        uint32_t* dh = (uint32_t*)R0;
        uint32_t* dl = (uint32_t*)R1;
#pragma unroll 8
        for (int i = tid; i < 8192; i += 256) {
            int n = i >> 6, c = i & 63;
            dh[n * (LDM / 2) + c] = __ldg(&bh[i]);
            dl[n * (LDM / 2) + c] = __ldg(&bl[i]);
        }
    }
    __syncthreads();

    // ---- stage 2 MMA: (h1h,B2h)+(h1h,B2l)+(h1l,B2h) ----
#pragma unroll
    for (int i = 0; i < 2; i++)
#pragma unroll
        for (int j = 0; j < 4; j++) wmma::fill_fragment(c[i][j], 0.f);

#pragma unroll 1
    for (int pass = 0; pass < 3; pass++) {
        const __nv_bfloat16* pa = (pass == 2) ? R3 : R2;
        const __nv_bfloat16* pb = (pass == 1) ? R1 : R0;
#pragma unroll
        for (int kk = 0; kk < 128; kk += 16) {
            wmma::fragment<wmma::matrix_a, 16, 16, 16, __nv_bfloat16, wmma::row_major> a[2];
            wmma::fragment<wmma::matrix_b, 16, 16, 16, __nv_bfloat16, wmma::col_major> b[4];
#pragma unroll
            for (int i = 0; i < 2; i++)
                wmma::load_matrix_sync(a[i], pa + (wm * 32 + i * 16) * LDM + kk, LDM);
#pragma unroll
            for (int j = 0; j < 4; j++)
                wmma::load_matrix_sync(b[j], pb + (wn * 64 + j * 16) * LDM + kk, LDM);
#pragma unroll
            for (int i = 0; i < 2; i++)
#pragma unroll
                for (int j = 0; j < 4; j++)
                    wmma::mma_sync(c[i][j], a[i], b[j], c[i][j]);
        }
    }
    __syncthreads();   // B2 dead; R0/R1 become sC again

    // ---- stage 2 epilogue: frags -> sC -> hr | h2pre ----
#pragma unroll
    for (int i = 0; i < 2; i++)
#pragma unroll
        for (int j = 0; j < 4; j++)
            wmma::store_matrix_sync(&sC[(wm * 32 + i * 16) * 132 + wn * 64 + j * 16],
                                    c[i][j], 132, wmma::mem_row_major);
    __syncthreads();

#pragma unroll 4
    for (int i = tid; i < 4096; i += 256) {
        int row = i >> 5;
        int c4 = (i & 31) * 4;
        int grow = row0 + row;
        if (grow >= NN) continue;
        float4 o;
        o.x = sC[row * 132 + c4];
        o.y = sC[row * 132 + c4 + 1];
        o.z = sC[row * 132 + c4 + 2];
        o.w = sC[row * 132 + c4 + 3];
        if (c4 < 64) *(float4*)(hr + (size_t)grow * 64 + c4) = o;
        else         *(float4*)(h2pre + (size_t)grow * 64 + c4 - 64) = o;
    }
}

// ------- fused: agg2 gather + h2 + attention + exp + weighted pooling -------
// warp per node; lane holds dims (2*lane, 2*lane+1)
__global__ __launch_bounds__(256) void post_fused_kernel(
    const float* __restrict__ h2pre, const float* __restrict__ hr,
    const float* __restrict__ x,
    const float* __restrict__ b2, const float* __restrict__ Wa,
    const float* __restrict__ ba, const float* __restrict__ ctx,
    float* __restrict__ gpool, float* __restrict__ gZ)
{
    __shared__ float sWa[64 * 32];
    __shared__ float sba[32], sctx[32];
    __shared__ float sb2[64];
    __shared__ float spool[64];
    __shared__ float sZ;
    const int tid = threadIdx.x;
    for (int f = tid; f < 2048; f += 256) sWa[f] = __ldg(&Wa[f]);
    if (tid < 32) { sba[tid] = __ldg(&ba[tid]); sctx[tid] = __ldg(&ctx[tid]); }
    if (tid < 64) { sb2[tid] = __ldg(&b2[tid]); spool[tid] = 0.f; }
    if (tid == 64) sZ = 0.f;
    __syncthreads();

    const int w = tid >> 5, lane = tid & 31;
    const int i = blockIdx.x * 8 + w;
    if (i < NN) {
        int beg = (i > 0) ? g_off[i - 1] : 0;
        int end = g_off[i];
        int d = end - beg;
        const float2* __restrict__ F = reinterpret_cast<const float2*>(h2pre);
        float ax = 0.f, ay = 0.f;
        int j = beg;
        for (; j + 1 < end; j += 2) {
            int s0 = __ldg(&g_srcs[j]);
            int s1 = __ldg(&g_srcs[j + 1]);
            float2 v0 = F[s0 * 32 + lane];
            float2 v1 = F[s1 * 32 + lane];
            ax += v0.x + v1.x;
            ay += v0.y + v1.y;
        }
        if (j < end) {
            int s = __ldg(&g_srcs[j]);
            float2 v = F[s * 32 + lane];
            ax += v.x; ay += v.y;
        }
        float inv = 1.0f / fmaxf((float)d, 1.0f);
        float2 hrv = reinterpret_cast<const float2*>(hr)[i * 32 + lane];
        float v0 = fmaxf(ax * inv + hrv.x + sb2[2 * lane], 0.f);
        float v1 = fmaxf(ay * inv + hrv.y + sb2[2 * lane + 1], 0.f);

        float acc = 0.f;
#pragma unroll
        for (int k = 0; k < 32; k++) {
            float hk0 = __shfl_sync(0xffffffffu, v0, k);
            float hk1 = __shfl_sync(0xffffffffu, v1, k);
            acc += hk0 * sWa[(2 * k) * 32 + lane] + hk1 * sWa[(2 * k + 1) * 32 + lane];
        }
        float t = tanhf(acc + sba[lane]) * sctx[lane];
#pragma unroll
        for (int o = 16; o; o >>= 1) t += __shfl_xor_sync(0xffffffffu, t, o);
        t += 0.4f * __ldg(&x[i * 64 + 63]);
        float e = expf(t);     // logits bounded: no max pass needed
        atomicAdd(&spool[2 * lane], e * v0);
        atomicAdd(&spool[2 * lane + 1], e * v1);
        if (lane == 0) atomicAdd(&sZ, e);
    }
    __syncthreads();
    if (tid < 64) atomicAdd(&gpool[tid], spool[tid]);
    if (tid == 64) atomicAdd(gZ, sZ);
}

// ---------------- tiny head --------------------------------------------------
__global__ __launch_bounds__(32) void final_kernel(
    const float* __restrict__ gpool, const float* __restrict__ gZ,
    const float* __restrict__ Wc1, const float* __restrict__ bc1,
    const float* __restrict__ Wc2, const float* __restrict__ bc2,
    float* __restrict__ out)
{
    const int j = threadIdx.x;
    const float inv = 1.0f / ((float)NN * (*gZ));
    float acc = bc1[j];
    for (int k = 0; k < 64; k++)
        acc += gpool[k] * inv * Wc1[k * 32 + j];
    float zv = fmaxf(acc, 0.f);
    float s = zv * Wc2[j];
#pragma unroll
    for (int o = 16; o; o >>= 1) s += __shfl_xor_sync(0xffffffffu, s, o);
    if (j == 0) out[0] = 1.0f / (1.0f + expf(-(s + bc2[0])));
}

// ---------------- launch ------------------------------------------------------
extern "C" void kernel_launch(void* const* d_in, const int* in_sizes, int n_in,
                              void* d_out, int out_size) {
    const float* x   = (const float*)d_in[0];
    const void*  ei  = d_in[1];
    const float* W1l = (const float*)d_in[2];
    const float* W1r = (const float*)d_in[3];
    const float* b1  = (const float*)d_in[4];
    const float* W2l = (const float*)d_in[5];
    const float* W2r = (const float*)d_in[6];
    const float* b2  = (const float*)d_in[7];
    const float* Wa  = (const float*)d_in[8];
    const float* ba  = (const float*)d_in[9];
    const float* ctx = (const float*)d_in[10];
    const float* Wc1 = (const float*)d_in[11];
    const float* bc1 = (const float*)d_in[12];
    const float* Wc2 = (const float*)d_in[13];
    const float* bc2 = (const float*)d_in[14];
    float* out = (float*)d_out;

    void *ppool, *pz, *pagg, *phr, *ph2pre;
    void *pB1h, *pB1l, *pB2h, *pB2l;
    cudaGetSymbolAddress(&ppool, g_pool);
    cudaGetSymbolAddress(&pz, g_Z);
    cudaGetSymbolAddress(&pagg, g_agg);
    cudaGetSymbolAddress(&phr, g_hr);
    cudaGetSymbolAddress(&ph2pre, g_h2pre);
    cudaGetSymbolAddress(&pB1h, g_B1h);
    cudaGetSymbolAddress(&pB1l, g_B1l);
    cudaGetSymbolAddress(&pB2h, g_B2h);
    cudaGetSymbolAddress(&pB2l, g_B2l);

    cudaFuncSetAttribute(gemm_fused_kernel, cudaFuncAttributeMaxDynamicSharedMemorySize, SMEM_WM);

    init_kernel<<<(NN + 255) / 256, 256>>>();
    detect_kernel<<<1, 32>>>(ei);
    hist_kernel<<<(EE + 255) / 256, 256>>>(ei);

    // parallel CSR offsets (3-phase scan)
    bsum_kernel<<<NB, 256>>>();
    bscan_kernel<<<1, 512>>>();
    offsets_kernel<<<NB, 256>>>();

    scatter_kernel<<<(EE + 255) / 256, 256>>>(ei);   // mutates g_off -> ends

    prep_weights_kernel<<<64, 256>>>(W1l, W1r, W2l, W2r);

    // agg1 = mean_agg(x)
    agg_kernel<<<(NN * 32 + 255) / 256, 256>>>(x, (float*)pagg);

    // fused GEMM1+GEMM2: [hr | h2pre] computed with h1 kept in smem
    gemm_fused_kernel<<<NTILES, 256, SMEM_WM>>>(
        (const float*)pagg, x,
        (const __nv_bfloat16*)pB1h, (const __nv_bfloat16*)pB1l,
        (const __nv_bfloat16*)pB2h, (const __nv_bfloat16*)pB2l,
        b1, (float*)phr, (float*)ph2pre);

    // fused: gather(mean h2pre) + h2 + attention + exp + weighted pool
    post_fused_kernel<<<(NN + 7) / 8, 256>>>(
        (const float*)ph2pre, (const float*)phr, x, b2, Wa, ba, ctx,
        (float*)ppool, (float*)pz);

    final_kernel<<<1, 32>>>((const float*)ppool, (const float*)pz,
                            Wc1, bc1, Wc2, bc2, out);
}